// round 16
// baseline (speedup 1.0000x reference)
#include <cuda_runtime.h>
#include <cuda_bf16.h>

// RepeatLayers: variable-length repeat_interleave along axis 0.
//   encoder_h: [N=8192, D=1024] fp32
//   repeats:   [N] int32 in [0, 8)
//   out:       [sum(repeats), D] fp32
//
// R16 = R14 (best: 26.66us) + ONE launch-shape change: occ 6 -> occ 7.
//   occ 7 => 7*148 = 1036 resident CTAs >= grid 1024: TRUE single wave,
//   eliminating R14's 136-CTA straggler tail (1024 = 888 + 136 at occ 6).
//   To fit 36 regs, the off[8] array is replaced by an incremental running
//   offset; the R14 load pipeline (reps -> group-A rows -> prefix -> REDUX
//   -> group-B rows -> stores) is preserved EXACTLY (R15 showed breaking it
//   costs more than the registers save).

#define N_ROWS 8192
#define D_ELEMS 1024
#define D_VEC4 (D_ELEMS / 4)     // 256 float4 per row
#define ROWS_PER_CTA 8
#define NB_CTAS (N_ROWS / ROWS_PER_CTA)   // 1024

// ---- L2 policy helpers ----
__device__ __forceinline__ float4 ldg_evict_last(const float4* p) {
    float4 v;
    asm volatile(
        "{\n\t"
        ".reg .b64 pol;\n\t"
        "createpolicy.fractional.L2::evict_last.b64 pol, 1.0;\n\t"
        "ld.global.nc.L2::cache_hint.v4.f32 {%0,%1,%2,%3}, [%4], pol;\n\t"
        "}"
        : "=f"(v.x), "=f"(v.y), "=f"(v.z), "=f"(v.w) : "l"(p));
    return v;
}
__device__ __forceinline__ void stg_evict_first(float4* p, float4 v) {
    asm volatile(
        "{\n\t"
        ".reg .b64 pol;\n\t"
        "createpolicy.fractional.L2::evict_first.b64 pol, 1.0;\n\t"
        "st.global.L2::cache_hint.v4.f32 [%0], {%1,%2,%3,%4}, pol;\n\t"
        "}"
        :: "l"(p), "f"(v.x), "f"(v.y), "f"(v.z), "f"(v.w) : "memory");
}

__global__ __launch_bounds__(256, 7)
void repeat_fused_kernel(const float* __restrict__ src,
                         const int* __restrict__ repeats,
                         float* __restrict__ out) {
    const int t = threadIdx.x;                    // 0..255
    const int lane = t & 31;
    const int wid = t >> 5;
    const int b = blockIdx.x;
    const int row0 = b * ROWS_PER_CTA;            // first of this CTA's 8 rows

    const int4* rp = reinterpret_cast<const int4*>(repeats);

    // --- This CTA's 8 repeat counts (two int4) ---
    const int4 ra = __ldg(&rp[2 * b]);
    const int4 rb = __ldg(&rp[2 * b + 1]);
    const int rep[ROWS_PER_CTA] = {ra.x, ra.y, ra.z, ra.w, rb.x, rb.y, rb.z, rb.w};

    // --- Front-batch group A row loads (rows 0..3), evict_last ---
    const float4* srcv = reinterpret_cast<const float4*>(src);
    float4 va[4];
#pragma unroll
    for (int i = 0; i < 4; i++) {
        if (rep[i] > 0) va[i] = ldg_evict_last(srcv + (size_t)(row0 + i) * D_VEC4 + t);
    }

    // --- Cooperative prefix sum: off0 = sum(repeats[0..row0)) ---
    const int n4 = row0 >> 2;                     // 2*b int4 words
    int sum = 0;
    for (int i = t; i < n4; i += 256) {
        int4 a = __ldg(&rp[i]);
        sum += a.x + a.y + a.z + a.w;
    }
    sum = __reduce_add_sync(0xFFFFFFFFu, sum);

    __shared__ int wsum[8];
    if (lane == 0) wsum[wid] = sum;
    __syncthreads();
    int cur;                                       // running output-row offset
    {
        int s2 = (lane < 8) ? wsum[lane] : 0;
        cur = __reduce_add_sync(0xFFFFFFFFu, s2);
    }

    float4* outv = reinterpret_cast<float4*>(out);

    // --- Issue group B loads (rows 4..7) before draining group A stores ---
    float4 vb[4];
#pragma unroll
    for (int i = 0; i < 4; i++) {
        if (rep[4 + i] > 0) vb[i] = ldg_evict_last(srcv + (size_t)(row0 + 4 + i) * D_VEC4 + t);
    }

    // --- Store group A (incremental offsets) ---
#pragma unroll
    for (int i = 0; i < 4; i++) {
        float4* o = outv + (size_t)cur * D_VEC4 + t;
#pragma unroll 8
        for (int r = 0; r < rep[i]; r++) {
            stg_evict_first(o, va[i]);
            o += D_VEC4;
        }
        cur += rep[i];
    }

    // --- Store group B ---
#pragma unroll
    for (int i = 0; i < 4; i++) {
        float4* o = outv + (size_t)cur * D_VEC4 + t;
#pragma unroll 8
        for (int r = 0; r < rep[4 + i]; r++) {
            stg_evict_first(o, vb[i]);
            o += D_VEC4;
        }
        cur += rep[4 + i];
    }
}

extern "C" void kernel_launch(void* const* d_in, const int* in_sizes, int n_in,
                              void* d_out, int out_size) {
    const float* encoder_h;
    const int* repeats;
    if (in_sizes[0] == N_ROWS * D_ELEMS) {
        encoder_h = (const float*)d_in[0];
        repeats   = (const int*)d_in[1];
    } else {
        encoder_h = (const float*)d_in[1];
        repeats   = (const int*)d_in[0];
    }
    float* out = (float*)d_out;
    (void)n_in; (void)out_size;

    repeat_fused_kernel<<<NB_CTAS, 256>>>(encoder_h, repeats, out);
}

// round 17
// speedup vs baseline: 1.1633x; 1.1633x over previous
#include <cuda_runtime.h>
#include <cuda_bf16.h>

// RepeatLayers: variable-length repeat_interleave along axis 0.
//   encoder_h: [N=8192, D=1024] fp32
//   repeats:   [N] int32 in [0, 8)
//   out:       [sum(repeats), D] fp32
//
// R17 = EXACT R14 (best: 26.66us) + ONE delta: output stores use __stcs
// (streaming .cs hint, single schedulable STG) instead of asm-volatile
// createpolicy+st.L2::cache_hint blocks. Removes the per-store memory
// clobber (which blocked compiler scheduling/CSE across ~28 stores per
// thread) while keeping streaming-eviction semantics.
// Everything else — load ordering (reps -> group-A rows -> prefix -> REDUX
// -> group-B rows -> stores), evict_last loads, off[8], RPC=8, grid 1024,
// launch_bounds(256,6) — unchanged.

#define N_ROWS 8192
#define D_ELEMS 1024
#define D_VEC4 (D_ELEMS / 4)     // 256 float4 per row
#define ROWS_PER_CTA 8
#define NB_CTAS (N_ROWS / ROWS_PER_CTA)   // 1024

__device__ __forceinline__ float4 ldg_evict_last(const float4* p) {
    float4 v;
    asm volatile(
        "{\n\t"
        ".reg .b64 pol;\n\t"
        "createpolicy.fractional.L2::evict_last.b64 pol, 1.0;\n\t"
        "ld.global.nc.L2::cache_hint.v4.f32 {%0,%1,%2,%3}, [%4], pol;\n\t"
        "}"
        : "=f"(v.x), "=f"(v.y), "=f"(v.z), "=f"(v.w) : "l"(p));
    return v;
}

__global__ __launch_bounds__(256, 6)
void repeat_fused_kernel(const float* __restrict__ src,
                         const int* __restrict__ repeats,
                         float* __restrict__ out) {
    const int t = threadIdx.x;                    // 0..255
    const int lane = t & 31;
    const int wid = t >> 5;
    const int row0 = blockIdx.x * ROWS_PER_CTA;   // first of this CTA's 8 rows

    // --- This CTA's 8 repeat counts (two int4) ---
    const int4 ra = __ldg(reinterpret_cast<const int4*>(&repeats[row0]));
    const int4 rb = __ldg(reinterpret_cast<const int4*>(&repeats[row0 + 4]));
    const int rep[ROWS_PER_CTA] = {ra.x, ra.y, ra.z, ra.w, rb.x, rb.y, rb.z, rb.w};

    // --- Front-batch group A row loads (rows 0..3), evict_last ---
    const float4* srcv = reinterpret_cast<const float4*>(src);
    float4 va[4];
#pragma unroll
    for (int i = 0; i < 4; i++) {
        if (rep[i] > 0) va[i] = ldg_evict_last(srcv + (size_t)(row0 + i) * D_VEC4 + t);
    }

    // --- Cooperative prefix sum: off0 = sum(repeats[0..row0)) ---
    const int n4 = row0 >> 2;                       // 2*blockIdx.x int4 words
    const int4* rp = reinterpret_cast<const int4*>(repeats);
    int sum = 0;
    for (int i = t; i < n4; i += 256) {
        int4 a = __ldg(&rp[i]);
        sum += a.x + a.y + a.z + a.w;
    }
    sum = __reduce_add_sync(0xFFFFFFFFu, sum);

    __shared__ int wsum[8];
    if (lane == 0) wsum[wid] = sum;
    __syncthreads();
    int off0;
    {
        int s2 = (lane < 8) ? wsum[lane] : 0;
        off0 = __reduce_add_sync(0xFFFFFFFFu, s2);
    }

    // Per-row output offsets.
    int off[ROWS_PER_CTA];
    off[0] = off0;
#pragma unroll
    for (int i = 1; i < ROWS_PER_CTA; i++) off[i] = off[i - 1] + rep[i - 1];

    float4* outv = reinterpret_cast<float4*>(out);

    // --- Issue group B loads (rows 4..7) before draining group A stores ---
    float4 vb[4];
#pragma unroll
    for (int i = 0; i < 4; i++) {
        if (rep[4 + i] > 0) vb[i] = ldg_evict_last(srcv + (size_t)(row0 + 4 + i) * D_VEC4 + t);
    }

    // --- Store group A (streaming stores) ---
#pragma unroll
    for (int i = 0; i < 4; i++) {
        float4* o = outv + (size_t)off[i] * D_VEC4 + t;
#pragma unroll 8
        for (int r = 0; r < rep[i]; r++) {
            __stcs(o, va[i]);
            o += D_VEC4;
        }
    }

    // --- Store group B ---
#pragma unroll
    for (int i = 0; i < 4; i++) {
        float4* o = outv + (size_t)off[4 + i] * D_VEC4 + t;
#pragma unroll 8
        for (int r = 0; r < rep[4 + i]; r++) {
            __stcs(o, vb[i]);
            o += D_VEC4;
        }
    }
}

extern "C" void kernel_launch(void* const* d_in, const int* in_sizes, int n_in,
                              void* d_out, int out_size) {
    const float* encoder_h;
    const int* repeats;
    if (in_sizes[0] == N_ROWS * D_ELEMS) {
        encoder_h = (const float*)d_in[0];
        repeats   = (const int*)d_in[1];
    } else {
        encoder_h = (const float*)d_in[1];
        repeats   = (const int*)d_in[0];
    }
    float* out = (float*)d_out;
    (void)n_in; (void)out_size;

    repeat_fused_kernel<<<NB_CTAS, 256>>>(encoder_h, repeats, out);
}